// round 14
// baseline (speedup 1.0000x reference)
#include <cuda_runtime.h>
#include <cuda_fp16.h>
#include <math.h>
#include <stdint.h>

#define Bdim 16
#define Ndim 128
#define Cdim 256
#define BN   2048
#define INVS 0.1767766952966369f

// ---------------- device globals ----------------
__device__ float g_q[BN*Cdim];
__device__ float g_k[BN*Cdim];
__device__ __align__(16) __half g_v16[BN*Cdim];
__device__ float g_WonT[Cdim*Cdim];
__device__ __align__(16) __half g_We_h[Cdim*Cdim];
__device__ __align__(16) __half g_Woe_h[Cdim*Cdim];

// ---------------- smem layout (bytes) ----------------
// Region 0: EDG (edge fp16 [128][264h] s528 = 67584) overlaid with
//           ATT (4 chunks x [128][72h] s144 = 73728). Region = 73728.
#define EDG   0
#define ATT   0
#define BS    73728     // slab ring: 6 x [256 rows][48B] = 73728
#define SQ_   147456    // q row, 256 f32
#define SBE_  148480    // be, 256 f32
#define SAGG_ 149504    // agg row, 256 f32
#define ESMEM 150528

// ---------------- PTX helpers ----------------
__device__ __forceinline__ uint32_t smem_u32(const void* p) {
    uint32_t a;
    asm("{ .reg .u64 t; cvta.to.shared.u64 t, %1; cvt.u32.u64 %0, t; }" : "=r"(a) : "l"(p));
    return a;
}
__device__ __forceinline__ void ldm4(uint32_t addr, uint32_t r[4]) {
    asm volatile("ldmatrix.sync.aligned.m8n8.x4.shared.b16 {%0,%1,%2,%3}, [%4];"
                 : "=r"(r[0]), "=r"(r[1]), "=r"(r[2]), "=r"(r[3]) : "r"(addr));
}
__device__ __forceinline__ void mma_f16(float d[4], const uint32_t a[4],
                                        uint32_t b0, uint32_t b1) {
    asm("mma.sync.aligned.m16n8k16.row.col.f32.f16.f16.f32 "
        "{%0,%1,%2,%3}, {%4,%5,%6,%7}, {%8,%9}, {%0,%1,%2,%3};"
        : "+f"(d[0]), "+f"(d[1]), "+f"(d[2]), "+f"(d[3])
        : "r"(a[0]), "r"(a[1]), "r"(a[2]), "r"(a[3]), "r"(b0), "r"(b1));
}
__device__ __forceinline__ uint32_t hpk(float a, float b) {
    __half2 t = __floats2half2_rn(a, b);
    return *reinterpret_cast<uint32_t*>(&t);
}
__device__ __forceinline__ void cp16(uint32_t d, const void* s) {
    asm volatile("cp.async.cg.shared.global [%0], [%1], 16;" :: "r"(d), "l"(s));
}
#define CP_COMMIT asm volatile("cp.async.commit_group;" ::: "memory")
#define CP_WAIT0  asm volatile("cp.async.wait_group 0;" ::: "memory")
#define CP_WAIT1  asm volatile("cp.async.wait_group 1;" ::: "memory")
#define CP_WAIT2  asm volatile("cp.async.wait_group 2;" ::: "memory")
#define CP_WAIT3  asm volatile("cp.async.wait_group 3;" ::: "memory")

// ---------------- merged setup kernel: weight prep + qkv projection ----------------
#define SASTR 36
#define SBSTR 260

__global__ __launch_bounds__(256) void setup_kernel(
    const float* __restrict__ X,
    const float* __restrict__ W0, const float* __restrict__ b0,
    const float* __restrict__ W1, const float* __restrict__ b1,
    const float* __restrict__ W2, const float* __restrict__ b2,
    const float* __restrict__ We, const float* __restrict__ Woe,
    const float* __restrict__ Won)
{
    __shared__ float sA[64*SASTR];
    __shared__ float sB[32*SBSTR];
    int blk = blockIdx.x;
    int tid = threadIdx.x;

    if (blk < 768) {
        int n = blk & 255, w = blk >> 8, k = tid;
        if (w == 2) { g_WonT[k*Cdim + n] = Won[n*Cdim + k]; return; }
        const float* W = w ? Woe : We;
        __half hi = __float2half(W[n*Cdim + k]);
        if (w) g_Woe_h[n*Cdim+k] = hi;
        else   g_We_h [n*Cdim+k] = hi;
        return;
    }

    int idx = blk - 768;
    int which = idx >> 5;
    int row0 = (idx & 31) * 64;
    const float* W    = (which==0) ? W0 : (which==1 ? W1 : W2);
    const float* bias = (which==0) ? b0 : (which==1 ? b1 : b2);
    int tx = tid & 31, ty = tid >> 5;

    float acc[8][8];
    #pragma unroll
    for (int m = 0; m < 8; m++)
        #pragma unroll
        for (int n = 0; n < 8; n++) acc[m][n] = 0.f;

    for (int kc = 0; kc < 8; kc++) {
        __syncthreads();
        #pragma unroll
        for (int it = 0; it < 2; it++) {
            int i2 = tid + it*256;
            int r = i2 >> 3, k4 = i2 & 7;
            float4 t = *(const float4*)(X + (size_t)(row0 + r)*Cdim + kc*32 + k4*4);
            *(float4*)(sA + r*SASTR + k4*4) = t;
        }
        #pragma unroll
        for (int it = 0; it < 8; it++) {
            int i2 = tid + it*256;
            int c = i2 >> 3, k4 = i2 & 7;
            float4 t = *(const float4*)(W + c*Cdim + kc*32 + k4*4);
            sB[(k4*4+0)*SBSTR + c] = t.x;
            sB[(k4*4+1)*SBSTR + c] = t.y;
            sB[(k4*4+2)*SBSTR + c] = t.z;
            sB[(k4*4+3)*SBSTR + c] = t.w;
        }
        __syncthreads();
        #pragma unroll
        for (int k = 0; k < 32; k++) {
            float a[8];
            #pragma unroll
            for (int mm = 0; mm < 4; mm++) {
                a[mm]   = sA[(ty*4+mm)*SASTR + k];
                a[4+mm] = sA[(32+ty*4+mm)*SASTR + k];
            }
            float4 p0 = *(const float4*)(sB + k*SBSTR + tx*4);
            float4 p1 = *(const float4*)(sB + k*SBSTR + 128 + tx*4);
            float bb[8] = {p0.x,p0.y,p0.z,p0.w,p1.x,p1.y,p1.z,p1.w};
            #pragma unroll
            for (int m = 0; m < 8; m++)
                #pragma unroll
                for (int n = 0; n < 8; n++)
                    acc[m][n] = fmaf(a[m], bb[n], acc[m][n]);
        }
    }
    #pragma unroll
    for (int mh = 0; mh < 2; mh++)
    #pragma unroll
    for (int mm = 0; mm < 4; mm++) {
        int m = mh*4 + mm;
        int rloc = mh*32 + ty*4 + mm;
        size_t grow = (size_t)(row0 + rloc) * Cdim;
        #pragma unroll
        for (int nh = 0; nh < 2; nh++) {
            int col0 = nh*128 + tx*4;
            float4 o;
            o.x = acc[m][nh*4+0] + bias[col0+0];
            o.y = acc[m][nh*4+1] + bias[col0+1];
            o.z = acc[m][nh*4+2] + bias[col0+2];
            o.w = acc[m][nh*4+3] + bias[col0+3];
            if (which == 0)      *(float4*)(g_q + grow + col0) = o;
            else if (which == 1) *(float4*)(g_k + grow + col0) = o;
            else {
                __half2 h0 = __floats2half2_rn(o.x, o.y);
                __half2 h1 = __floats2half2_rn(o.z, o.w);
                uint2 u;
                u.x = *reinterpret_cast<uint32_t*>(&h0);
                u.y = *reinterpret_cast<uint32_t*>(&h1);
                *(uint2*)(g_v16 + grow + col0) = u;
            }
        }
    }
}

// ---------------- B k-slab loader (256 threads, 512 cp16) ----------------
__device__ __forceinline__ void loadSlab(uint32_t sbuf, const __half* W, int ks, int tid) {
    #pragma unroll
    for (int it = 0; it < 2; it++) {
        int idx = tid + it*256;
        int row = idx >> 1, half = idx & 1;
        cp16(sbuf + row*48 + half*16, W + row*Cdim + ks*16 + half*8);
    }
}

// ---------------- one k16 slab: warp tile m64 x n64, 8 LDSM -> 32 HMMA ----------------
template<bool FROM_ATT>
__device__ __forceinline__ void gslab(uint32_t aBase, uint32_t bBase, int ks,
                                      float acc[4][8][4]) {
    uint32_t a[4][4], bf[4][4];
    #pragma unroll
    for (int mt = 0; mt < 4; mt++) {
        uint32_t aaddr;
        if (FROM_ATT) aaddr = aBase + (ks>>2)*18432 + (ks&3)*32 + mt*(16*144);
        else          aaddr = aBase + ks*32 + mt*(16*528);
        ldm4(aaddr, a[mt]);
    }
    #pragma unroll
    for (int t = 0; t < 4; t++) ldm4(bBase + t*768, bf[t]);
    #pragma unroll
    for (int mt = 0; mt < 4; mt++)
        #pragma unroll
        for (int t = 0; t < 4; t++) {
            mma_f16(acc[mt][t*2+0], a[mt], bf[t][0], bf[t][1]);
            mma_f16(acc[mt][t*2+1], a[mt], bf[t][2], bf[t][3]);
        }
}

// ---------------- fused edge mega-kernel: one 256-thr CTA per (b,i) ----------------
__global__ __launch_bounds__(256, 1) void edge_fused(
    const float* __restrict__ edge,
    const float* __restrict__ be, const float* __restrict__ boe,
    const float* __restrict__ bon,
    float* __restrict__ edge_out, float* __restrict__ node_out)
{
    extern __shared__ char sm[];
    uint32_t sb = smem_u32(sm);
    const int tid  = threadIdx.x;
    const int lane = tid & 31, wid = tid >> 5;
    const int bi   = blockIdx.x;          // b*128 + i
    const int b    = bi >> 7;

    // prologue: slabs 0..3 (prefetch depth 4)
    loadSlab(sb + BS + 0*12288, g_We_h, 0, tid); CP_COMMIT;
    loadSlab(sb + BS + 1*12288, g_We_h, 1, tid); CP_COMMIT;
    loadSlab(sb + BS + 2*12288, g_We_h, 2, tid); CP_COMMIT;
    loadSlab(sb + BS + 3*12288, g_We_h, 3, tid); CP_COMMIT;

    float* sQ   = (float*)(sm + SQ_);
    float* sBe  = (float*)(sm + SBE_);
    float* sAgg = (float*)(sm + SAGG_);
    sQ[tid]  = g_q[(size_t)bi*Cdim + tid];
    sBe[tid] = be[tid];

    // edge full tile -> fp16 in smem (128 rows x 256 cols)
    const float4* erow = (const float4*)(edge + (size_t)bi*(Ndim*Cdim));
    #pragma unroll
    for (int it = 0; it < 32; it++) {
        int idx = tid + it*256;            // 0..8191 float4
        float4 v = erow[idx];
        int j = idx >> 6, c4 = idx & 63;
        __half2 h0 = __floats2half2_rn(v.x, v.y);
        __half2 h1 = __floats2half2_rn(v.z, v.w);
        uint2 u;
        u.x = *reinterpret_cast<uint32_t*>(&h0);
        u.y = *reinterpret_cast<uint32_t*>(&h1);
        *(uint2*)(sm + EDG + j*528 + c4*8) = u;
    }

    // warp grid: 2 m-groups x 4 n-groups; warp tile m64 x n64
    const int wm = wid >> 2, wn = wid & 3;
    const uint32_t aoffE = (uint32_t)((wm*64 + (lane & 15))*528 + ((lane >> 4) << 4));
    const uint32_t aoffT = (uint32_t)((wm*64 + (lane & 15))*144 + ((lane >> 4) << 4));
    const uint32_t boff  = (uint32_t)((wn*64 + (lane & 7) + ((lane & 16) ? 8 : 0))*48 + ((lane & 8) << 1));

    float acc[4][8][4];
    #pragma unroll
    for (int mt = 0; mt < 4; mt++)
        #pragma unroll
        for (int g = 0; g < 8; g++)
            #pragma unroll
            for (int r = 0; r < 4; r++) acc[mt][g][r] = 0.f;

    // ============ 32 k16-slabs: 0-15 GEMM1 (We), 16-31 GEMM2 (Woe) ============
    #pragma unroll 1
    for (int ks = 0; ks < 32; ks++) {
        if (ks == 16) {
            __syncthreads();   // all warps done reading EDG
            // gating epilogue: e -> attn into the EDG/ATT shared region
            #pragma unroll
            for (int mt = 0; mt < 4; mt++) {
                int rbase = wm*64 + mt*16 + (lane >> 2);
                const float* k0p = g_k + (size_t)(b*Ndim + rbase)*Cdim;
                const float* k1p = k0p + 8*Cdim;
                #pragma unroll
                for (int t = 0; t < 8; t++) {
                    int c_loc = t*8 + ((lane & 3) << 1);
                    int c = wn*64 + c_loc;
                    float2 kk0 = *(const float2*)(k0p + c);
                    float2 kk1 = *(const float2*)(k1p + c);
                    float q0 = sQ[c], q1 = sQ[c+1];
                    float be0 = sBe[c], be1 = sBe[c+1];
                    float e00 = acc[mt][t][0] + be0, e01 = acc[mt][t][1] + be1;
                    float e10 = acc[mt][t][2] + be0, e11 = acc[mt][t][3] + be1;
                    float a00 = q0*kk0.x*INVS*(e00*e00 + e00);
                    float a01 = q1*kk0.y*INVS*(e01*e01 + e01);
                    float a10 = q0*kk1.x*INVS*(e10*e10 + e10);
                    float a11 = q1*kk1.y*INVS*(e11*e11 + e11);
                    *(uint32_t*)(sm + ATT + wn*18432 + rbase*144 + c_loc*2)     = hpk(a00, a01);
                    *(uint32_t*)(sm + ATT + wn*18432 + (rbase+8)*144 + c_loc*2) = hpk(a10, a11);
                    acc[mt][t][0] = 0.f; acc[mt][t][1] = 0.f;
                    acc[mt][t][2] = 0.f; acc[mt][t][3] = 0.f;
                }
            }
        }

        if      (ks <= 28) { CP_WAIT3; }
        else if (ks == 29) { CP_WAIT2; }
        else if (ks == 30) { CP_WAIT1; }
        else               { CP_WAIT0; }
        __syncthreads();   // slab ks visible (+EDG at ks=0, +ATT at ks=16)

        uint32_t bbuf = sb + BS + (uint32_t)(ks % 6) * 12288 + boff;
        if (ks < 16) gslab<false>(sb + EDG + aoffE, bbuf, ks, acc);
        else         gslab<true >(sb + ATT + aoffT, bbuf, ks - 16, acc);

        // prefetch slab ks+4 into ring buf (ks+4)%6 (held slab ks-2; its
        // readers passed sync(ks-1) < sync(ks)). Safe.
        int nx = ks + 4;
        if (nx < 32) {
            const __half* src = (nx < 16) ? g_We_h : g_Woe_h;
            loadSlab(sb + BS + (uint32_t)(nx % 6) * 12288, src, nx & 15, tid);
            CP_COMMIT;
        }
    }

    // ---- edge_out epilogue ----
    #pragma unroll
    for (int mt = 0; mt < 4; mt++) {
        int rbase = wm*64 + mt*16 + (lane >> 2);
        float* out0 = edge_out + ((size_t)bi*Ndim + rbase)*Cdim;
        float* out1 = out0 + 8*Cdim;
        #pragma unroll
        for (int t = 0; t < 8; t++) {
            int n = wn*64 + t*8 + ((lane & 3) << 1);
            float b0 = boe[n], b1 = boe[n+1];
            float2 o0, o1;
            o0.x = acc[mt][t][0] + b0;   o0.y = acc[mt][t][1] + b1;
            o1.x = acc[mt][t][2] + b0;   o1.y = acc[mt][t][3] + b1;
            *(float2*)(out0 + n) = o0;
            *(float2*)(out1 + n) = o1;
        }
    }

    // ---- softmax over 128 j (ATT unchanged since the ks=16 barrier) ----
    {
        int c = tid;
        int ch = c >> 6, off = c & 63;
        const __half* vbase = g_v16 + (size_t)(b*Ndim)*Cdim + c;
        float s = 0.f, ag = 0.f;
        #pragma unroll 4
        for (int j = 0; j < Ndim; j++) {
            float a = __half2float(*(const __half*)(sm + ATT + ch*18432 + j*144 + off*2));
            float p = __expf(a);
            s += p;
            ag += p * __half2float(vbase[(size_t)j*Cdim]);
        }
        sAgg[c] = ag / s;
    }
    __syncthreads();

    // ---- node_out = agg @ Won^T + bon ----
    {
        int c = tid;
        float accn = bon[c];
        #pragma unroll 8
        for (int k = 0; k < Cdim; k++)
            accn = fmaf(sAgg[k], g_WonT[(size_t)k*Cdim + c], accn);
        node_out[(size_t)bi*Cdim + c] = accn;
    }
}

// ---------------- launch ----------------
extern "C" void kernel_launch(void* const* d_in, const int* in_sizes, int n_in,
                              void* d_out, int out_size)
{
    const float* node = (const float*)d_in[0];
    const float* edge = (const float*)d_in[1];
    const float* Wq  = (const float*)d_in[2];  const float* bq  = (const float*)d_in[3];
    const float* Wk  = (const float*)d_in[4];  const float* bk  = (const float*)d_in[5];
    const float* Wv  = (const float*)d_in[6];  const float* bv  = (const float*)d_in[7];
    const float* We  = (const float*)d_in[8];  const float* be  = (const float*)d_in[9];
    const float* Woe = (const float*)d_in[10]; const float* boe = (const float*)d_in[11];
    const float* Won = (const float*)d_in[12]; const float* bon = (const float*)d_in[13];

    float* out = (float*)d_out;
    float* node_out = out;                       // [B,N,C]
    float* edge_out = out + (size_t)BN*Cdim;     // [B,N,N,C]

    cudaFuncSetAttribute(edge_fused, cudaFuncAttributeMaxDynamicSharedMemorySize, ESMEM);

    setup_kernel<<<768 + 96, 256>>>(node, Wq, bq, Wk, bk, Wv, bv, We, Woe, Won);
    edge_fused<<<BN, 256, ESMEM>>>(edge, be, boe, bon, edge_out, node_out);
}

// round 15
// speedup vs baseline: 1.2771x; 1.2771x over previous
#include <cuda_runtime.h>
#include <cuda_fp16.h>
#include <math.h>
#include <stdint.h>

#define Bdim 16
#define Ndim 128
#define Cdim 256
#define BN   2048
#define INVS 0.1767766952966369f

// ---------------- device globals ----------------
__device__ float g_q[BN*Cdim];
__device__ float g_k[BN*Cdim];
__device__ __align__(16) __half g_v16[BN*Cdim];
__device__ float g_WonT[Cdim*Cdim];
__device__ __align__(16) __half g_We_h[Cdim*Cdim];
__device__ __align__(16) __half g_Woe_h[Cdim*Cdim];
__device__ float g_ps [2*BN*Cdim];
__device__ float g_pag[2*BN*Cdim];

// ---------------- smem layout (bytes) ----------------
#define EDG   0        // edge fp16 [64][264h] s528 = 33792 ; reused as v tile in GEMM2
#define ATT   33792    // attn fp16 4 chunks x [64][72h] s144  = 36864
#define BS    70656    // B slab ring: 3 x [256 rows][48B]     = 36864
#define SQ_   107520
#define SBE_  108544
#define SBOE_ 109568
#define ESMEM 110592

// ---------------- PTX helpers ----------------
__device__ __forceinline__ uint32_t smem_u32(const void* p) {
    uint32_t a;
    asm("{ .reg .u64 t; cvta.to.shared.u64 t, %1; cvt.u32.u64 %0, t; }" : "=r"(a) : "l"(p));
    return a;
}
__device__ __forceinline__ void ldm4(uint32_t addr, uint32_t r[4]) {
    asm volatile("ldmatrix.sync.aligned.m8n8.x4.shared.b16 {%0,%1,%2,%3}, [%4];"
                 : "=r"(r[0]), "=r"(r[1]), "=r"(r[2]), "=r"(r[3]) : "r"(addr));
}
__device__ __forceinline__ void mma_f16(float d[4], const uint32_t a[4],
                                        uint32_t b0, uint32_t b1) {
    asm("mma.sync.aligned.m16n8k16.row.col.f32.f16.f16.f32 "
        "{%0,%1,%2,%3}, {%4,%5,%6,%7}, {%8,%9}, {%0,%1,%2,%3};"
        : "+f"(d[0]), "+f"(d[1]), "+f"(d[2]), "+f"(d[3])
        : "r"(a[0]), "r"(a[1]), "r"(a[2]), "r"(a[3]), "r"(b0), "r"(b1));
}
__device__ __forceinline__ uint32_t hpk(float a, float b) {
    __half2 t = __floats2half2_rn(a, b);
    return *reinterpret_cast<uint32_t*>(&t);
}
__device__ __forceinline__ void cp16(uint32_t d, const void* s) {
    asm volatile("cp.async.cg.shared.global [%0], [%1], 16;" :: "r"(d), "l"(s));
}
#define CP_COMMIT asm volatile("cp.async.commit_group;" ::: "memory")
#define CP_WAIT0  asm volatile("cp.async.wait_group 0;" ::: "memory")
#define CP_WAIT1  asm volatile("cp.async.wait_group 1;" ::: "memory")

// ---------------- merged setup kernel: weight prep + qkv projection ----------------
#define SASTR 36
#define SBSTR 260

__global__ __launch_bounds__(256) void setup_kernel(
    const float* __restrict__ X,
    const float* __restrict__ W0, const float* __restrict__ b0,
    const float* __restrict__ W1, const float* __restrict__ b1,
    const float* __restrict__ W2, const float* __restrict__ b2,
    const float* __restrict__ We, const float* __restrict__ Woe,
    const float* __restrict__ Won)
{
    __shared__ float sA[64*SASTR];
    __shared__ float sB[32*SBSTR];
    int blk = blockIdx.x;
    int tid = threadIdx.x;

    if (blk < 768) {
        int n = blk & 255, w = blk >> 8, k = tid;
        if (w == 2) { g_WonT[k*Cdim + n] = Won[n*Cdim + k]; return; }
        const float* W = w ? Woe : We;
        __half hi = __float2half(W[n*Cdim + k]);
        if (w) g_Woe_h[n*Cdim+k] = hi;
        else   g_We_h [n*Cdim+k] = hi;
        return;
    }

    int idx = blk - 768;
    int which = idx >> 5;
    int row0 = (idx & 31) * 64;
    const float* W    = (which==0) ? W0 : (which==1 ? W1 : W2);
    const float* bias = (which==0) ? b0 : (which==1 ? b1 : b2);
    int tx = tid & 31, ty = tid >> 5;

    float acc[8][8];
    #pragma unroll
    for (int m = 0; m < 8; m++)
        #pragma unroll
        for (int n = 0; n < 8; n++) acc[m][n] = 0.f;

    for (int kc = 0; kc < 8; kc++) {
        __syncthreads();
        #pragma unroll
        for (int it = 0; it < 2; it++) {
            int i2 = tid + it*256;
            int r = i2 >> 3, k4 = i2 & 7;
            float4 t = *(const float4*)(X + (size_t)(row0 + r)*Cdim + kc*32 + k4*4);
            *(float4*)(sA + r*SASTR + k4*4) = t;
        }
        #pragma unroll
        for (int it = 0; it < 8; it++) {
            int i2 = tid + it*256;
            int c = i2 >> 3, k4 = i2 & 7;
            float4 t = *(const float4*)(W + c*Cdim + kc*32 + k4*4);
            sB[(k4*4+0)*SBSTR + c] = t.x;
            sB[(k4*4+1)*SBSTR + c] = t.y;
            sB[(k4*4+2)*SBSTR + c] = t.z;
            sB[(k4*4+3)*SBSTR + c] = t.w;
        }
        __syncthreads();
        #pragma unroll
        for (int k = 0; k < 32; k++) {
            float a[8];
            #pragma unroll
            for (int mm = 0; mm < 4; mm++) {
                a[mm]   = sA[(ty*4+mm)*SASTR + k];
                a[4+mm] = sA[(32+ty*4+mm)*SASTR + k];
            }
            float4 p0 = *(const float4*)(sB + k*SBSTR + tx*4);
            float4 p1 = *(const float4*)(sB + k*SBSTR + 128 + tx*4);
            float bb[8] = {p0.x,p0.y,p0.z,p0.w,p1.x,p1.y,p1.z,p1.w};
            #pragma unroll
            for (int m = 0; m < 8; m++)
                #pragma unroll
                for (int n = 0; n < 8; n++)
                    acc[m][n] = fmaf(a[m], bb[n], acc[m][n]);
        }
    }
    #pragma unroll
    for (int mh = 0; mh < 2; mh++)
    #pragma unroll
    for (int mm = 0; mm < 4; mm++) {
        int m = mh*4 + mm;
        int rloc = mh*32 + ty*4 + mm;
        size_t grow = (size_t)(row0 + rloc) * Cdim;
        #pragma unroll
        for (int nh = 0; nh < 2; nh++) {
            int col0 = nh*128 + tx*4;
            float4 o;
            o.x = acc[m][nh*4+0] + bias[col0+0];
            o.y = acc[m][nh*4+1] + bias[col0+1];
            o.z = acc[m][nh*4+2] + bias[col0+2];
            o.w = acc[m][nh*4+3] + bias[col0+3];
            if (which == 0)      *(float4*)(g_q + grow + col0) = o;
            else if (which == 1) *(float4*)(g_k + grow + col0) = o;
            else {
                __half2 h0 = __floats2half2_rn(o.x, o.y);
                __half2 h1 = __floats2half2_rn(o.z, o.w);
                uint2 u;
                u.x = *reinterpret_cast<uint32_t*>(&h0);
                u.y = *reinterpret_cast<uint32_t*>(&h1);
                *(uint2*)(g_v16 + grow + col0) = u;
            }
        }
    }
}

// ---------------- B k-slab loader: W[n 0..255][k ks*16..+16] -> [256 rows][48B] ----------------
__device__ __forceinline__ void loadSlab(uint32_t sbuf, const __half* W, int ks, int tid) {
    #pragma unroll
    for (int it = 0; it < 2; it++) {
        int idx = tid + it*256;
        int row = idx >> 1, half = idx & 1;
        cp16(sbuf + row*48 + half*16, W + row*Cdim + ks*16 + half*8);
    }
}
// ---- v tile quarter-chunk loader into EDG region (16 rows x 256 halfs) ----
__device__ __forceinline__ void loadVq(uint32_t sb, int b, int jrow0, int chunk, int tid) {
    #pragma unroll
    for (int it = 0; it < 2; it++) {
        int idx = tid + it*256;                 // 0..511
        int r = chunk*16 + (idx >> 5), part = idx & 31;
        cp16(sb + EDG + r*528 + part*16,
             g_v16 + (size_t)(b*Ndim + jrow0 + r)*Cdim + part*8);
    }
}

// ---------------- one k16 slab of the 64x256 warp-tiled GEMM (m32 x n64 per warp) ----------------
template<bool FROM_ATT>
__device__ __forceinline__ void gslab(uint32_t aBase, uint32_t bBase, int ks,
                                      float acc[2][8][4]) {
    uint32_t a[2][4];
    #pragma unroll
    for (int mt = 0; mt < 2; mt++) {
        uint32_t aaddr;
        if (FROM_ATT) aaddr = aBase + (ks>>2)*9216 + (ks&3)*32 + mt*(16*144);
        else          aaddr = aBase + ks*32 + mt*(16*528);
        ldm4(aaddr, a[mt]);
    }
    #pragma unroll
    for (int t = 0; t < 4; t++) {
        uint32_t bf[4];
        ldm4(bBase + t*768, bf);
        #pragma unroll
        for (int mt = 0; mt < 2; mt++) {
            mma_f16(acc[mt][t*2+0], a[mt], bf[0], bf[1]);
            mma_f16(acc[mt][t*2+1], a[mt], bf[2], bf[3]);
        }
    }
}

// ---------------- fused edge mega-kernel: one CTA per (b,i,j-half) ----------------
__global__ __launch_bounds__(256, 2) void edge_fused(
    const float* __restrict__ edge,
    const float* __restrict__ be, const float* __restrict__ boe,
    float* __restrict__ edge_out)
{
    extern __shared__ char sm[];
    uint32_t sb = smem_u32(sm);
    const int tid  = threadIdx.x;
    const int lane = tid & 31, wid = tid >> 5;
    const int bi   = blockIdx.x >> 1;
    const int jh   = blockIdx.x & 1;
    const int b    = bi >> 7;
    const int jrow0 = jh * 64;

    // prologue: slabs 0 and 1 of the 32-slab stream (We 0..15, Woe 16..31)
    loadSlab(sb + BS,         g_We_h, 0, tid); CP_COMMIT;
    loadSlab(sb + BS + 12288, g_We_h, 1, tid); CP_COMMIT;

    float* sQ   = (float*)(sm + SQ_);
    float* sBe  = (float*)(sm + SBE_);
    float* sBoe = (float*)(sm + SBOE_);
    sQ[tid]   = g_q[(size_t)bi*Cdim + tid];
    sBe[tid]  = be[tid];
    sBoe[tid] = boe[tid];

    // edge half-tile -> fp16 in smem (64 rows x 256 cols)
    const float4* erow = (const float4*)(edge + ((size_t)bi*Ndim + jrow0)*Cdim);
    #pragma unroll
    for (int it = 0; it < 16; it++) {
        int idx = tid + it*256;
        float4 v = erow[idx];
        int j = idx >> 6, c4 = idx & 63;
        __half2 h0 = __floats2half2_rn(v.x, v.y);
        __half2 h1 = __floats2half2_rn(v.z, v.w);
        uint2 u;
        u.x = *reinterpret_cast<uint32_t*>(&h0);
        u.y = *reinterpret_cast<uint32_t*>(&h1);
        *(uint2*)(sm + EDG + j*528 + c4*8) = u;
    }

    // warp grid: 2 m-groups x 4 n-groups; warp tile m32 x n64
    const int wm = wid & 1, wn = wid >> 1;
    const uint32_t aoffE = sb + EDG + (uint32_t)((wm*32 + (lane & 15))*528 + ((lane >> 4) << 4));
    const uint32_t aoffT = sb + ATT + (uint32_t)((wm*32 + (lane & 15))*144 + ((lane >> 4) << 4));
    const uint32_t boff  = (uint32_t)((wn*64 + (lane & 7) + ((lane & 16) ? 8 : 0))*48 + ((lane & 8) << 1));

    float acc[2][8][4];
    #pragma unroll
    for (int mt = 0; mt < 2; mt++)
        #pragma unroll
        for (int g = 0; g < 8; g++)
            #pragma unroll
            for (int r = 0; r < 4; r++) acc[mt][g][r] = 0.f;

    // ============ unified 32-slab ring (3 buffers, 1 sync per slab) ============
    #pragma unroll 1
    for (int ks = 0; ks < 32; ks++) {
        if (ks == 16) {
            // gating epilogue: e -> attn (ATT), reset acc. Published by iter-16 sync.
            #pragma unroll
            for (int mt = 0; mt < 2; mt++) {
                int rbase = wm*32 + mt*16 + (lane >> 2);
                const float* k0p = g_k + (size_t)(b*Ndim + jrow0 + rbase)*Cdim;
                const float* k1p = k0p + 8*Cdim;
                #pragma unroll
                for (int t = 0; t < 8; t++) {
                    int c_loc = t*8 + ((lane & 3) << 1);
                    int c = wn*64 + c_loc;
                    float2 kk0 = *(const float2*)(k0p + c);
                    float2 kk1 = *(const float2*)(k1p + c);
                    float q0 = sQ[c], q1 = sQ[c+1];
                    float be0 = sBe[c], be1 = sBe[c+1];
                    float e00 = acc[mt][t][0] + be0, e01 = acc[mt][t][1] + be1;
                    float e10 = acc[mt][t][2] + be0, e11 = acc[mt][t][3] + be1;
                    float a00 = q0*kk0.x*INVS*(e00*e00 + e00);
                    float a01 = q1*kk0.y*INVS*(e01*e01 + e01);
                    float a10 = q0*kk1.x*INVS*(e10*e10 + e10);
                    float a11 = q1*kk1.y*INVS*(e11*e11 + e11);
                    *(uint32_t*)(sm + ATT + wn*9216 + rbase*144 + c_loc*2)     = hpk(a00, a01);
                    *(uint32_t*)(sm + ATT + wn*9216 + (rbase+8)*144 + c_loc*2) = hpk(a10, a11);
                    acc[mt][t][0] = 0.f; acc[mt][t][1] = 0.f;
                    acc[mt][t][2] = 0.f; acc[mt][t][3] = 0.f;
                }
            }
        }

        if (ks < 31) { CP_WAIT1; } else { CP_WAIT0; }
        __syncthreads();   // slab ks visible (+EDG at ks=0, +ATT at ks=16)

        uint32_t bbuf = sb + BS + (uint32_t)(ks % 3) * 12288 + boff;
        if (ks < 16) gslab<false>(aoffE, bbuf, ks, acc);
        else         gslab<true >(aoffT, bbuf, ks - 16, acc);

        // prefetch slab ks+2 (ring-safe per R9 invariant); piggyback v-tile
        // quarter loads into EDG at ks=16..19 (EDG dead after GEMM1; all warps
        // passed sync(16) before these issue).
        int nx = ks + 2;
        if (nx < 32) {
            if (ks >= 16 && ks < 20) loadVq(sb, b, jrow0, ks - 16, tid);
            const __half* src = (nx < 16) ? g_We_h : g_Woe_h;
            loadSlab(sb + BS + (uint32_t)(nx % 3) * 12288, src, nx & 15, tid);
            CP_COMMIT;
        }
    }

    // ---- edge_out epilogue ----
    #pragma unroll
    for (int mt = 0; mt < 2; mt++) {
        int rbase = wm*32 + mt*16 + (lane >> 2);
        float* out0 = edge_out + ((size_t)bi*Ndim + jrow0 + rbase)*Cdim;
        float* out1 = out0 + 8*Cdim;
        #pragma unroll
        for (int t = 0; t < 8; t++) {
            int n = wn*64 + t*8 + ((lane & 3) << 1);
            float2 o0, o1;
            o0.x = acc[mt][t][0] + sBoe[n];   o0.y = acc[mt][t][1] + sBoe[n+1];
            o1.x = acc[mt][t][2] + sBoe[n];   o1.y = acc[mt][t][3] + sBoe[n+1];
            *(float2*)(out0 + n) = o0;
            *(float2*)(out1 + n) = o1;
        }
    }

    // ---- local softmax partials over 64 j; v from SMEM (EDG region) ----
    {
        int c = tid;
        int ch = c >> 6, off = c & 63;
        float s = 0.f, ag = 0.f;
        #pragma unroll 8
        for (int j = 0; j < 64; j++) {
            float a = __half2float(*(const __half*)(sm + ATT + ch*9216 + j*144 + off*2));
            float vv = __half2float(*(const __half*)(sm + EDG + j*528 + c*2));
            float p = __expf(a);
            s += p;
            ag += p * vv;
        }
        g_ps [(size_t)jh*BN*Cdim + (size_t)bi*Cdim + c] = s;
        g_pag[(size_t)jh*BN*Cdim + (size_t)bi*Cdim + c] = ag;
    }
}

// ---------------- node_final: combine partials + node matvec (8 bi per CTA) ----------------
__global__ __launch_bounds__(256) void node_final(
    const float* __restrict__ bon, float* __restrict__ node_out)
{
    __shared__ float sAgg[8*Cdim];
    int tid = threadIdx.x;
    int bi0 = blockIdx.x * 8;

    #pragma unroll
    for (int r8 = 0; r8 < 8; r8++) {
        size_t o = (size_t)(bi0 + r8)*Cdim + tid;
        float s  = g_ps [o] + g_ps [(size_t)BN*Cdim + o];
        float ag = g_pag[o] + g_pag[(size_t)BN*Cdim + o];
        sAgg[r8*Cdim + tid] = ag / s;
    }
    __syncthreads();

    float acc[8];
    #pragma unroll
    for (int r8 = 0; r8 < 8; r8++) acc[r8] = 0.f;
    #pragma unroll 4
    for (int k = 0; k < Cdim; k++) {
        float w = g_WonT[(size_t)k*Cdim + tid];
        #pragma unroll
        for (int r8 = 0; r8 < 8; r8++)
            acc[r8] = fmaf(sAgg[r8*Cdim + k], w, acc[r8]);
    }
    float bb = bon[tid];
    #pragma unroll
    for (int r8 = 0; r8 < 8; r8++)
        node_out[(size_t)(bi0 + r8)*Cdim + tid] = acc[r8] + bb;
}

// ---------------- launch ----------------
extern "C" void kernel_launch(void* const* d_in, const int* in_sizes, int n_in,
                              void* d_out, int out_size)
{
    const float* node = (const float*)d_in[0];
    const float* edge = (const float*)d_in[1];
    const float* Wq  = (const float*)d_in[2];  const float* bq  = (const float*)d_in[3];
    const float* Wk  = (const float*)d_in[4];  const float* bk  = (const float*)d_in[5];
    const float* Wv  = (const float*)d_in[6];  const float* bv  = (const float*)d_in[7];
    const float* We  = (const float*)d_in[8];  const float* be  = (const float*)d_in[9];
    const float* Woe = (const float*)d_in[10]; const float* boe = (const float*)d_in[11];
    const float* Won = (const float*)d_in[12]; const float* bon = (const float*)d_in[13];

    float* out = (float*)d_out;
    float* node_out = out;                       // [B,N,C]
    float* edge_out = out + (size_t)BN*Cdim;     // [B,N,N,C]

    cudaFuncSetAttribute(edge_fused, cudaFuncAttributeMaxDynamicSharedMemorySize, ESMEM);

    setup_kernel<<<768 + 96, 256>>>(node, Wq, bq, Wk, bk, Wv, bv, We, Woe, Won);
    edge_fused<<<2*BN, 256, ESMEM>>>(edge, be, boe, edge_out);
    node_final<<<BN/8, 256>>>(bon, node_out);
}

// round 16
// speedup vs baseline: 1.3166x; 1.0310x over previous
#include <cuda_runtime.h>
#include <cuda_fp16.h>
#include <math.h>
#include <stdint.h>

#define Bdim 16
#define Ndim 128
#define Cdim 256
#define BN   2048
#define INVS 0.1767766952966369f

// ---------------- device globals ----------------
__device__ float g_q[BN*Cdim];
__device__ __align__(16) __half g_k16[BN*Cdim];
__device__ __align__(16) __half g_v16[BN*Cdim];
__device__ float g_WonT[Cdim*Cdim];
__device__ __align__(16) __half g_We_h[Cdim*Cdim];
__device__ __align__(16) __half g_Woe_h[Cdim*Cdim];
__device__ float g_ps [2*BN*Cdim];
__device__ float g_pag[2*BN*Cdim];

// ---------------- smem layout (bytes) ----------------
#define EDG   0        // edge fp16 [64][264h] s528 = 33792 ; reused as v tile in GEMM2
#define ATT   33792    // attn fp16 4 chunks x [64][72h] s144 = 36864 ; holds k16 during GEMM1
#define BS    70656    // B slab ring: 3 x [256 rows][48B]    = 36864
#define SQ_   107520
#define SBE_  108544
#define SBOE_ 109568
#define ESMEM 110592

// ---------------- PTX helpers ----------------
__device__ __forceinline__ uint32_t smem_u32(const void* p) {
    uint32_t a;
    asm("{ .reg .u64 t; cvta.to.shared.u64 t, %1; cvt.u32.u64 %0, t; }" : "=r"(a) : "l"(p));
    return a;
}
__device__ __forceinline__ void ldm4(uint32_t addr, uint32_t r[4]) {
    asm volatile("ldmatrix.sync.aligned.m8n8.x4.shared.b16 {%0,%1,%2,%3}, [%4];"
                 : "=r"(r[0]), "=r"(r[1]), "=r"(r[2]), "=r"(r[3]) : "r"(addr));
}
__device__ __forceinline__ void mma_f16(float d[4], const uint32_t a[4],
                                        uint32_t b0, uint32_t b1) {
    asm("mma.sync.aligned.m16n8k16.row.col.f32.f16.f16.f32 "
        "{%0,%1,%2,%3}, {%4,%5,%6,%7}, {%8,%9}, {%0,%1,%2,%3};"
        : "+f"(d[0]), "+f"(d[1]), "+f"(d[2]), "+f"(d[3])
        : "r"(a[0]), "r"(a[1]), "r"(a[2]), "r"(a[3]), "r"(b0), "r"(b1));
}
__device__ __forceinline__ uint32_t hpk(float a, float b) {
    __half2 t = __floats2half2_rn(a, b);
    return *reinterpret_cast<uint32_t*>(&t);
}
__device__ __forceinline__ float2 h2f2(uint32_t u) {
    __half2 h = *reinterpret_cast<__half2*>(&u);
    return __half22float2(h);
}
__device__ __forceinline__ void cp16(uint32_t d, const void* s) {
    asm volatile("cp.async.cg.shared.global [%0], [%1], 16;" :: "r"(d), "l"(s));
}
#define CP_COMMIT asm volatile("cp.async.commit_group;" ::: "memory")
#define CP_WAIT0  asm volatile("cp.async.wait_group 0;" ::: "memory")
#define CP_WAIT1  asm volatile("cp.async.wait_group 1;" ::: "memory")

// ---------------- merged setup kernel: weight prep + qkv projection (32-row tiles) ----------------
#define SASTR 36
#define SBSTR 260

__global__ __launch_bounds__(256) void setup_kernel(
    const float* __restrict__ X,
    const float* __restrict__ W0, const float* __restrict__ b0,
    const float* __restrict__ W1, const float* __restrict__ b1,
    const float* __restrict__ W2, const float* __restrict__ b2,
    const float* __restrict__ We, const float* __restrict__ Woe,
    const float* __restrict__ Won)
{
    __shared__ float sA[32*SASTR];
    __shared__ float sB[32*SBSTR];
    int blk = blockIdx.x;
    int tid = threadIdx.x;

    if (blk < 768) {
        int n = blk & 255, w = blk >> 8, k = tid;
        if (w == 2) { g_WonT[k*Cdim + n] = Won[n*Cdim + k]; return; }
        const float* W = w ? Woe : We;
        __half hi = __float2half(W[n*Cdim + k]);
        if (w) g_Woe_h[n*Cdim+k] = hi;
        else   g_We_h [n*Cdim+k] = hi;
        return;
    }

    int idx = blk - 768;                 // 0..191
    int which = idx >> 6;                // 0,1,2
    int row0 = (idx & 63) * 32;
    const float* W    = (which==0) ? W0 : (which==1 ? W1 : W2);
    const float* bias = (which==0) ? b0 : (which==1 ? b1 : b2);
    int tx = tid & 31, ty = tid >> 5;

    float acc[4][8];
    #pragma unroll
    for (int m = 0; m < 4; m++)
        #pragma unroll
        for (int n = 0; n < 8; n++) acc[m][n] = 0.f;

    for (int kc = 0; kc < 8; kc++) {
        __syncthreads();
        {   // load A tile 32x32 (256 float4, 1 per thread)
            int r = tid >> 3, k4 = tid & 7;
            float4 t = *(const float4*)(X + (size_t)(row0 + r)*Cdim + kc*32 + k4*4);
            *(float4*)(sA + r*SASTR + k4*4) = t;
        }
        #pragma unroll
        for (int it = 0; it < 8; it++) {
            int i2 = tid + it*256;
            int c = i2 >> 3, k4 = i2 & 7;
            float4 t = *(const float4*)(W + c*Cdim + kc*32 + k4*4);
            sB[(k4*4+0)*SBSTR + c] = t.x;
            sB[(k4*4+1)*SBSTR + c] = t.y;
            sB[(k4*4+2)*SBSTR + c] = t.z;
            sB[(k4*4+3)*SBSTR + c] = t.w;
        }
        __syncthreads();
        #pragma unroll
        for (int k = 0; k < 32; k++) {
            float a[4];
            #pragma unroll
            for (int mm = 0; mm < 4; mm++)
                a[mm] = sA[(ty*4+mm)*SASTR + k];
            float4 p0 = *(const float4*)(sB + k*SBSTR + tx*4);
            float4 p1 = *(const float4*)(sB + k*SBSTR + 128 + tx*4);
            float bb[8] = {p0.x,p0.y,p0.z,p0.w,p1.x,p1.y,p1.z,p1.w};
            #pragma unroll
            for (int m = 0; m < 4; m++)
                #pragma unroll
                for (int n = 0; n < 8; n++)
                    acc[m][n] = fmaf(a[m], bb[n], acc[m][n]);
        }
    }
    #pragma unroll
    for (int mm = 0; mm < 4; mm++) {
        int rloc = ty*4 + mm;
        size_t grow = (size_t)(row0 + rloc) * Cdim;
        #pragma unroll
        for (int nh = 0; nh < 2; nh++) {
            int col0 = nh*128 + tx*4;
            float4 o;
            o.x = acc[mm][nh*4+0] + bias[col0+0];
            o.y = acc[mm][nh*4+1] + bias[col0+1];
            o.z = acc[mm][nh*4+2] + bias[col0+2];
            o.w = acc[mm][nh*4+3] + bias[col0+3];
            if (which == 0) *(float4*)(g_q + grow + col0) = o;
            else {
                __half2 h0 = __floats2half2_rn(o.x, o.y);
                __half2 h1 = __floats2half2_rn(o.z, o.w);
                uint2 u;
                u.x = *reinterpret_cast<uint32_t*>(&h0);
                u.y = *reinterpret_cast<uint32_t*>(&h1);
                if (which == 1) *(uint2*)(g_k16 + grow + col0) = u;
                else            *(uint2*)(g_v16 + grow + col0) = u;
            }
        }
    }
}

// ---------------- B k-slab loader: W[n 0..255][k ks*16..+16] -> [256 rows][48B] ----------------
__device__ __forceinline__ void loadSlab(uint32_t sbuf, const __half* W, int ks, int tid) {
    #pragma unroll
    for (int it = 0; it < 2; it++) {
        int idx = tid + it*256;
        int row = idx >> 1, half = idx & 1;
        cp16(sbuf + row*48 + half*16, W + row*Cdim + ks*16 + half*8);
    }
}
// ---- v tile quarter loader into EDG region (16 rows x 256 halfs) ----
__device__ __forceinline__ void loadVq(uint32_t sb, int b, int jrow0, int chunk, int tid) {
    #pragma unroll
    for (int it = 0; it < 2; it++) {
        int idx = tid + it*256;
        int r = chunk*16 + (idx >> 5), part = idx & 31;
        cp16(sb + EDG + r*528 + part*16,
             g_v16 + (size_t)(b*Ndim + jrow0 + r)*Cdim + part*8);
    }
}
// ---- k tile quarter loader into ATT region, in attn-chunk layout ----
// element (row r, col c) -> ATT + (c>>6)*9216 + r*144 + (c&63)*2
__device__ __forceinline__ void loadKq(uint32_t sb, int b, int jrow0, int chunk, int tid) {
    #pragma unroll
    for (int it = 0; it < 2; it++) {
        int idx = tid + it*256;
        int r = chunk*16 + (idx >> 5), blk = idx & 31;   // c = blk*8
        cp16(sb + ATT + (blk >> 3)*9216 + r*144 + (blk & 7)*16,
             g_k16 + (size_t)(b*Ndim + jrow0 + r)*Cdim + blk*8);
    }
}

// ---------------- one k16 slab of the 64x256 warp-tiled GEMM (m32 x n64 per warp) ----------------
template<bool FROM_ATT>
__device__ __forceinline__ void gslab(uint32_t aBase, uint32_t bBase, int ks,
                                      float acc[2][8][4]) {
    uint32_t a[2][4];
    #pragma unroll
    for (int mt = 0; mt < 2; mt++) {
        uint32_t aaddr;
        if (FROM_ATT) aaddr = aBase + (ks>>2)*9216 + (ks&3)*32 + mt*(16*144);
        else          aaddr = aBase + ks*32 + mt*(16*528);
        ldm4(aaddr, a[mt]);
    }
    #pragma unroll
    for (int t = 0; t < 4; t++) {
        uint32_t bf[4];
        ldm4(bBase + t*768, bf);
        #pragma unroll
        for (int mt = 0; mt < 2; mt++) {
            mma_f16(acc[mt][t*2+0], a[mt], bf[0], bf[1]);
            mma_f16(acc[mt][t*2+1], a[mt], bf[2], bf[3]);
        }
    }
}

// ---------------- fused edge mega-kernel: one CTA per (b,i,j-half) ----------------
__global__ __launch_bounds__(256, 2) void edge_fused(
    const float* __restrict__ edge,
    const float* __restrict__ be, const float* __restrict__ boe,
    float* __restrict__ edge_out)
{
    extern __shared__ char sm[];
    uint32_t sb = smem_u32(sm);
    const int tid  = threadIdx.x;
    const int lane = tid & 31, wid = tid >> 5;
    const int bi   = blockIdx.x >> 1;
    const int jh   = blockIdx.x & 1;
    const int b    = bi >> 7;
    const int jrow0 = jh * 64;

    // prologue: slabs 0 and 1 of the 32-slab stream (We 0..15, Woe 16..31)
    loadSlab(sb + BS,         g_We_h, 0, tid); CP_COMMIT;
    loadSlab(sb + BS + 12288, g_We_h, 1, tid); CP_COMMIT;

    float* sQ   = (float*)(sm + SQ_);
    float* sBe  = (float*)(sm + SBE_);
    float* sBoe = (float*)(sm + SBOE_);
    sQ[tid]   = g_q[(size_t)bi*Cdim + tid];
    sBe[tid]  = be[tid];
    sBoe[tid] = boe[tid];

    // edge half-tile -> fp16 in smem (64 rows x 256 cols)
    const float4* erow = (const float4*)(edge + ((size_t)bi*Ndim + jrow0)*Cdim);
    #pragma unroll
    for (int it = 0; it < 16; it++) {
        int idx = tid + it*256;
        float4 v = erow[idx];
        int j = idx >> 6, c4 = idx & 63;
        __half2 h0 = __floats2half2_rn(v.x, v.y);
        __half2 h1 = __floats2half2_rn(v.z, v.w);
        uint2 u;
        u.x = *reinterpret_cast<uint32_t*>(&h0);
        u.y = *reinterpret_cast<uint32_t*>(&h1);
        *(uint2*)(sm + EDG + j*528 + c4*8) = u;
    }

    // warp grid: 2 m-groups x 4 n-groups; warp tile m32 x n64
    const int wm = wid & 1, wn = wid >> 1;
    const uint32_t aoffE = sb + EDG + (uint32_t)((wm*32 + (lane & 15))*528 + ((lane >> 4) << 4));
    const uint32_t aoffT = sb + ATT + (uint32_t)((wm*32 + (lane & 15))*144 + ((lane >> 4) << 4));
    const uint32_t boff  = (uint32_t)((wn*64 + (lane & 7) + ((lane & 16) ? 8 : 0))*48 + ((lane & 8) << 1));

    float acc[2][8][4];
    #pragma unroll
    for (int mt = 0; mt < 2; mt++)
        #pragma unroll
        for (int g = 0; g < 8; g++)
            #pragma unroll
            for (int r = 0; r < 4; r++) acc[mt][g][r] = 0.f;

    // ============ unified 32-slab ring (3 buffers, 1 sync per slab) ============
    #pragma unroll 1
    for (int ks = 0; ks < 32; ks++) {
        if (ks == 16) {
            // gating epilogue: e -> attn. k16 sits in ATT at EXACTLY the attn
            // addresses (same-owner read-then-write; cp.async groups drained
            // and published by sync(4..15)).
            #pragma unroll
            for (int mt = 0; mt < 2; mt++) {
                int rbase = wm*32 + mt*16 + (lane >> 2);
                #pragma unroll
                for (int t = 0; t < 8; t++) {
                    int c_loc = t*8 + ((lane & 3) << 1);
                    int c = wn*64 + c_loc;
                    uint32_t* p0 = (uint32_t*)(sm + ATT + wn*9216 + rbase*144 + c_loc*2);
                    uint32_t* p1 = (uint32_t*)(sm + ATT + wn*9216 + (rbase+8)*144 + c_loc*2);
                    float2 kk0 = h2f2(*p0);
                    float2 kk1 = h2f2(*p1);
                    float q0 = sQ[c], q1 = sQ[c+1];
                    float be0 = sBe[c], be1 = sBe[c+1];
                    float e00 = acc[mt][t][0] + be0, e01 = acc[mt][t][1] + be1;
                    float e10 = acc[mt][t][2] + be0, e11 = acc[mt][t][3] + be1;
                    float a00 = q0*kk0.x*INVS*(e00*e00 + e00);
                    float a01 = q1*kk0.y*INVS*(e01*e01 + e01);
                    float a10 = q0*kk1.x*INVS*(e10*e10 + e10);
                    float a11 = q1*kk1.y*INVS*(e11*e11 + e11);
                    *p0 = hpk(a00, a01);
                    *p1 = hpk(a10, a11);
                    acc[mt][t][0] = 0.f; acc[mt][t][1] = 0.f;
                    acc[mt][t][2] = 0.f; acc[mt][t][3] = 0.f;
                }
            }
        }

        if (ks < 31) { CP_WAIT1; } else { CP_WAIT0; }
        __syncthreads();   // slab ks visible (+EDG at ks=0, +ATT attn at ks=16)

        uint32_t bbuf = sb + BS + (uint32_t)(ks % 3) * 12288 + boff;
        if (ks < 16) gslab<false>(aoffE, bbuf, ks, acc);
        else         gslab<true >(aoffT, bbuf, ks - 16, acc);

        // prefetch slab ks+2 (ring-safe); piggyback k-tile loads into ATT at
        // ks=0..3 (ATT dead until 16) and v-tile loads into EDG at ks=16..19
        // (EDG dead after GEMM1).
        int nx = ks + 2;
        if (nx < 32) {
            if (ks < 4)                loadKq(sb, b, jrow0, ks, tid);
            else if (ks >= 16 && ks < 20) loadVq(sb, b, jrow0, ks - 16, tid);
            const __half* src = (nx < 16) ? g_We_h : g_Woe_h;
            loadSlab(sb + BS + (uint32_t)(nx % 3) * 12288, src, nx & 15, tid);
            CP_COMMIT;
        }
    }

    // ---- edge_out epilogue ----
    #pragma unroll
    for (int mt = 0; mt < 2; mt++) {
        int rbase = wm*32 + mt*16 + (lane >> 2);
        float* out0 = edge_out + ((size_t)bi*Ndim + jrow0 + rbase)*Cdim;
        float* out1 = out0 + 8*Cdim;
        #pragma unroll
        for (int t = 0; t < 8; t++) {
            int n = wn*64 + t*8 + ((lane & 3) << 1);
            float2 o0, o1;
            o0.x = acc[mt][t][0] + sBoe[n];   o0.y = acc[mt][t][1] + sBoe[n+1];
            o1.x = acc[mt][t][2] + sBoe[n];   o1.y = acc[mt][t][3] + sBoe[n+1];
            *(float2*)(out0 + n) = o0;
            *(float2*)(out1 + n) = o1;
        }
    }

    // ---- local softmax partials over 64 j; v from SMEM (EDG region) ----
    {
        int c = tid;
        int ch = c >> 6, off = c & 63;
        float s = 0.f, ag = 0.f;
        #pragma unroll 8
        for (int j = 0; j < 64; j++) {
            float a = __half2float(*(const __half*)(sm + ATT + ch*9216 + j*144 + off*2));
            float vv = __half2float(*(const __half*)(sm + EDG + j*528 + c*2));
            float p = __expf(a);
            s += p;
            ag += p * vv;
        }
        g_ps [(size_t)jh*BN*Cdim + (size_t)bi*Cdim + c] = s;
        g_pag[(size_t)jh*BN*Cdim + (size_t)bi*Cdim + c] = ag;
    }
}

// ---------------- node_final: combine partials + node matvec (8 bi per CTA) ----------------
__global__ __launch_bounds__(256) void node_final(
    const float* __restrict__ bon, float* __restrict__ node_out)
{
    __shared__ float sAgg[8*Cdim];
    int tid = threadIdx.x;
    int bi0 = blockIdx.x * 8;

    #pragma unroll
    for (int r8 = 0; r8 < 8; r8++) {
        size_t o = (size_t)(bi0 + r8)*Cdim + tid;
        float s  = g_ps [o] + g_ps [(size_t)BN*Cdim + o];
        float ag = g_pag[o] + g_pag[(size_t)BN*Cdim + o];
        sAgg[r8*Cdim + tid] = ag / s;
    }
    __syncthreads();

    float acc[8];
    #pragma unroll
    for (int r8 = 0; r8 < 8; r8++) acc[r8] = 0.f;
    #pragma unroll 4
    for (int k = 0; k < Cdim; k++) {
        float w = g_WonT[(size_t)k*Cdim + tid];
        #pragma unroll
        for (int r8 = 0; r8 < 8; r8++)
            acc[r8] = fmaf(sAgg[r8*Cdim + k], w, acc[r8]);
    }
    float bb = bon[tid];
    #pragma unroll
    for (int r8 = 0; r8 < 8; r8++)
        node_out[(size_t)(bi0 + r8)*Cdim + tid] = acc[r8] + bb;
}

// ---------------- launch ----------------
extern "C" void kernel_launch(void* const* d_in, const int* in_sizes, int n_in,
                              void* d_out, int out_size)
{
    const float* node = (const float*)d_in[0];
    const float* edge = (const float*)d_in[1];
    const float* Wq  = (const float*)d_in[2];  const float* bq  = (const float*)d_in[3];
    const float* Wk  = (const float*)d_in[4];  const float* bk  = (const float*)d_in[5];
    const float* Wv  = (const float*)d_in[6];  const float* bv  = (const float*)d_in[7];
    const float* We  = (const float*)d_in[8];  const float* be  = (const float*)d_in[9];
    const float* Woe = (const float*)d_in[10]; const float* boe = (const float*)d_in[11];
    const float* Won = (const float*)d_in[12]; const float* bon = (const float*)d_in[13];

    float* out = (float*)d_out;
    float* node_out = out;                       // [B,N,C]
    float* edge_out = out + (size_t)BN*Cdim;     // [B,N,N,C]

    cudaFuncSetAttribute(edge_fused, cudaFuncAttributeMaxDynamicSharedMemorySize, ESMEM);

    setup_kernel<<<768 + 192, 256>>>(node, Wq, bq, Wk, bk, Wv, bv, We, Woe, Won);
    edge_fused<<<2*BN, 256, ESMEM>>>(edge, be, boe, edge_out);
    node_final<<<BN/8, 256>>>(bon, node_out);
}